// round 9
// baseline (speedup 1.0000x reference)
#include <cuda_runtime.h>
#include <math.h>

#define NROWS 32768
#define KDICT 512
#define DDIM  64
#define ZN    2097152   // 32*64*32*32

// scratch (no allocations allowed)
__device__ float g_c2[512];
__device__ float g_avg[512];
__device__ float g_kldd;
__device__ float g_cont;

__device__ __forceinline__ float half_prec_from(const float* varq) {
    float vq = __ldg(varq);
    float p  = fminf(1.0f / fmaxf(vq, 1e-5f), 1e5f);
    return 0.5f * p;
}

// ---------------------------------------------------------------------------
// prep: zero accumulators (must run every launch for graph determinism) and
// compute codebook squared norms.
// ---------------------------------------------------------------------------
__global__ void prep_kernel(const float* __restrict__ cb) {
    int t = blockIdx.x * blockDim.x + threadIdx.x; // 0..511
    if (t == 0) { g_kldd = 0.f; g_cont = 0.f; }
    if (t < 512) {
        g_avg[t] = 0.f;
        const float4* row = (const float4*)(cb + (size_t)t * 64);
        float s = 0.f;
        #pragma unroll
        for (int i = 0; i < 16; i++) {
            float4 v = __ldg(row + i);
            s += v.x*v.x + v.y*v.y + v.z*v.z + v.w*v.w;
        }
        g_c2[t] = s;
    }
}

// ---------------------------------------------------------------------------
// main fused kernel: 1 block = 32 rows.
// smem layout (floats):
//   sL   [32][513]          0     .. 16415   logits -> encodings (in place)
//   sZ   [64][32]           16416 .. 18463   z tile transposed [d][r]
//   sCB  8448               18464 .. 26911   codebook chunk (two layouts)
//   sAvg [512]              26912 .. 27423   block-partial avg probs
//   sScal[2]                27424 .. 27425   kldd / cont partials
//   sZ2  [32]               27426 .. 27457   row squared norms
// total 27458 floats = 109832 bytes
// ---------------------------------------------------------------------------
__global__ void __launch_bounds__(256, 2)
main_kernel(const float* __restrict__ z, const float* __restrict__ varq,
            const float* __restrict__ cb, const float* __restrict__ gum,
            float* __restrict__ out) {
    extern __shared__ float sm[];
    float* sL    = sm;
    float* sZ    = sm + 16416;
    float* sCB   = sm + 18464;
    float* sAvg  = sm + 26912;
    float* sScal = sm + 27424;
    float* sZ2   = sm + 27426;

    const int t     = threadIdx.x;
    const int nbase = blockIdx.x * 32;
    const int b     = nbase >> 10;     // batch index (1024 rows per batch)
    const int nin   = nbase & 1023;    // w*32+h offset within batch
    const float hp  = half_prec_from(varq);

    for (int i = t; i < 512; i += 256) sAvg[i] = 0.f;
    if (t < 2) sScal[t] = 0.f;

    // ---- load z tile transposed: sZ[d*32 + r] (coalesced global reads) ----
    const float* zb = z + (size_t)b * 65536 + nin;
    for (int idx = t; idx < 2048; idx += 256) {
        int d = idx >> 5, r = idx & 31;
        sZ[idx] = __ldg(zb + (size_t)d * 1024 + r);
    }
    __syncthreads();
    if (t < 32) {
        float s = 0.f;
        #pragma unroll 8
        for (int d = 0; d < 64; d++) { float v = sZ[d*32 + t]; s += v*v; }
        sZ2[t] = s;   // consumed after the kc-loop barriers below
    }

    // =========================== Phase A: ip = z @ cb^T ====================
    // thread tile: rows r0..r0+3, cols c0 + 32*j (j=0..15)
    const int r0 = (t & 7) * 4;
    const int c0 = t >> 3;             // 0..31
    float acc[4][16];
    #pragma unroll
    for (int i = 0; i < 4; i++)
        #pragma unroll
        for (int j = 0; j < 16; j++) acc[i][j] = 0.f;

    const float2* Z2  = (const float2*)sZ;      // [d][16 row-pairs]
    const float2* CBP = (const float2*)sCB;     // [d][66] pairs (cp, cp+64)

    for (int kc = 0; kc < 4; kc++) {
        __syncthreads();
        // load 128 codebook rows, store transposed+paired:
        //   CBP[d][cp] = { cb[base+cp][d], cb[base+cp+64][d] }
        for (int idx = t; idx < 2048; idx += 256) {
            int c = idx >> 4, dq = idx & 15;
            float4 v = __ldg((const float4*)cb + (size_t)(kc*128 + c)*16 + dq);
            int h = c >> 6, cp = c & 63;
            int base = cp*2 + h;
            sCB[(dq*4+0)*132 + base] = v.x;
            sCB[(dq*4+1)*132 + base] = v.y;
            sCB[(dq*4+2)*132 + base] = v.z;
            sCB[(dq*4+3)*132 + base] = v.w;
        }
        __syncthreads();
        const int j0 = kc * 4;
        #pragma unroll 4
        for (int d = 0; d < 64; d++) {
            float2 a01 = Z2[d*16 + (t & 7)*2];       // rows r0, r0+1
            float2 a23 = Z2[d*16 + (t & 7)*2 + 1];   // rows r0+2, r0+3
            float2 b02 = CBP[d*66 + c0];             // cols c0, c0+64   -> j0, j0+2
            float2 b13 = CBP[d*66 + c0 + 32];        // cols c0+32,c0+96 -> j0+1, j0+3
            acc[0][j0+0] += a01.x*b02.x; acc[1][j0+0] += a01.y*b02.x;
            acc[2][j0+0] += a23.x*b02.x; acc[3][j0+0] += a23.y*b02.x;
            acc[0][j0+1] += a01.x*b13.x; acc[1][j0+1] += a01.y*b13.x;
            acc[2][j0+1] += a23.x*b13.x; acc[3][j0+1] += a23.y*b13.x;
            acc[0][j0+2] += a01.x*b02.y; acc[1][j0+2] += a01.y*b02.y;
            acc[2][j0+2] += a23.x*b02.y; acc[3][j0+2] += a23.y*b02.y;
            acc[0][j0+3] += a01.x*b13.y; acc[1][j0+3] += a01.y*b13.y;
            acc[2][j0+3] += a23.x*b13.y; acc[3][j0+3] += a23.y*b13.y;
        }
    }
    __syncthreads();

    // write logits: logit = -hp*(z2 + c2 - 2*ip)
    #pragma unroll
    for (int i = 0; i < 4; i++) {
        float z2v = sZ2[r0 + i];
        #pragma unroll
        for (int j = 0; j < 16; j++) {
            int c = c0 + 32*j;
            float dist = z2v + __ldg(&g_c2[c]) - 2.f*acc[i][j];
            sL[(r0+i)*513 + c] = -hp * dist;
        }
    }
    __syncthreads();

    // ================= Phase B: softmax / gumbel-softmax (warp per row) ====
    {
        const int w = t >> 5, lane = t & 31;
        float pacc[16];
        #pragma unroll
        for (int j = 0; j < 16; j++) pacc[j] = 0.f;
        float kldd_local = 0.f;
        const float* gumb = gum + (size_t)nbase * 512;

        for (int rr = 0; rr < 4; rr++) {
            int r = w*4 + rr;
            float v[16];
            #pragma unroll
            for (int j = 0; j < 16; j++) v[j] = sL[r*513 + lane + 32*j];
            float m = v[0];
            #pragma unroll
            for (int j = 1; j < 16; j++) m = fmaxf(m, v[j]);
            #pragma unroll
            for (int o = 16; o; o >>= 1) m = fmaxf(m, __shfl_xor_sync(~0u, m, o));

            float e[16], s1 = 0.f, t1 = 0.f;
            #pragma unroll
            for (int j = 0; j < 16; j++) {
                float lc = fminf(fmaxf(v[j] - m, -50.f), 50.f);
                v[j] = lc;
                float ee = __expf(lc);
                e[j] = ee;
                s1 += ee; t1 += ee * lc;
            }
            #pragma unroll
            for (int o = 16; o; o >>= 1) {
                s1 += __shfl_xor_sync(~0u, s1, o);
                t1 += __shfl_xor_sync(~0u, t1, o);
            }
            float inv1 = 1.0f / s1;
            #pragma unroll
            for (int j = 0; j < 16; j++) pacc[j] += e[j] * inv1;
            kldd_local += t1 * inv1 - __logf(s1);

            // gumbel-softmax encodings, temperature 0.5
            // PRECISION-CRITICAL: inner log must be accurate near u=1, where
            // __logf's absolute error (~5e-7) exceeds |log(u)| ~ (1-u).
            const float* gr = gumb + (size_t)r * 512;
            #pragma unroll
            for (int j = 0; j < 16; j++) {
                float u  = __ldg(gr + lane + 32*j);
                float lu = (u > 0.5f) ? log1pf(u - 1.0f)    // exact u-1, accurate near 1
                                      : logf(u + 1e-10f);   // accurate, handles u=0
                float g  = -logf(1e-10f - lu);
                v[j] = (v[j] + g) * 2.0f;
            }
            float m2 = v[0];
            #pragma unroll
            for (int j = 1; j < 16; j++) m2 = fmaxf(m2, v[j]);
            #pragma unroll
            for (int o = 16; o; o >>= 1) m2 = fmaxf(m2, __shfl_xor_sync(~0u, m2, o));
            float s2 = 0.f;
            #pragma unroll
            for (int j = 0; j < 16; j++) { float ee = __expf(v[j] - m2); e[j] = ee; s2 += ee; }
            #pragma unroll
            for (int o = 16; o; o >>= 1) s2 += __shfl_xor_sync(~0u, s2, o);
            float inv2 = 1.0f / s2;
            #pragma unroll
            for (int j = 0; j < 16; j++) sL[r*513 + lane + 32*j] = e[j] * inv2;
        }
        if (lane == 0) atomicAdd(&sScal[0], kldd_local);
        #pragma unroll
        for (int j = 0; j < 16; j++) atomicAdd(&sAvg[lane + 32*j], pacc[j]);
    }
    __syncthreads();

    // flush block partials
    for (int i = t; i < 512; i += 256) atomicAdd(&g_avg[i], sAvg[i]);
    if (t == 0) atomicAdd(&g_kldd, sScal[0]);

    // ======================= Phase C: z_q = enc @ cb =======================
    {
        const int rc = t & 31, dg = t >> 5;   // row, d-group (8 d each)
        float accq[8];
        #pragma unroll
        for (int q = 0; q < 8; q++) accq[q] = 0.f;

        for (int kc = 0; kc < 4; kc++) {
            __syncthreads();
            for (int idx = t; idx < 2048; idx += 256)
                ((float4*)sCB)[idx] = __ldg((const float4*)cb + (size_t)kc*2048 + idx);
            __syncthreads();
            #pragma unroll 4
            for (int k = 0; k < 128; k++) {
                float e = sL[rc*513 + kc*128 + k];
                float4 c1 = ((const float4*)sCB)[k*16 + dg*2];
                float4 c2 = ((const float4*)sCB)[k*16 + dg*2 + 1];
                accq[0] += e*c1.x; accq[1] += e*c1.y; accq[2] += e*c1.z; accq[3] += e*c1.w;
                accq[4] += e*c2.x; accq[5] += e*c2.y; accq[6] += e*c2.z; accq[7] += e*c2.w;
            }
        }

        float contl = 0.f;
        float* ob = out + (size_t)b * 65536 + nin;
        #pragma unroll
        for (int q = 0; q < 8; q++) {
            int d = dg*8 + q;
            float zv = sZ[d*32 + rc];
            float df = zv - accq[q];
            contl += df * df;
            ob[(size_t)d * 1024 + rc] = accq[q];   // coalesced across rc
        }
        atomicAdd(&sScal[1], contl);
    }
    __syncthreads();
    if (t == 0) atomicAdd(&g_cont, sScal[1]);
}

// ---------------------------------------------------------------------------
// finalize: loss + perplexity
// ---------------------------------------------------------------------------
__global__ void final_kernel(const float* __restrict__ varq,
                             float* __restrict__ out, int out_size) {
    __shared__ float red[512];
    int t = threadIdx.x;
    float ap = fmaxf(g_avg[t] * (1.0f / 32768.0f), 1e-10f);
    red[t] = ap * __logf(ap + 1e-10f);
    __syncthreads();
    for (int o = 256; o; o >>= 1) {
        if (t < o) red[t] += red[t + o];
        __syncthreads();
    }
    if (t == 0) {
        float hp    = half_prec_from(varq);
        float loss  = (g_kldd + hp * g_cont) * (1.0f / 32.0f);
        float perpl = __expf(-red[0]);
        if (out_size >= ZN + 2)      { out[ZN] = loss; out[ZN + 1] = perpl; }
        else if (out_size == 2)      { out[0]  = loss; out[1]      = perpl; }
        // out_size == ZN: tensor-only output, nothing extra to write
    }
}

// ---------------------------------------------------------------------------
extern "C" void kernel_launch(void* const* d_in, const int* in_sizes, int n_in,
                              void* d_out, int out_size) {
    // identify inputs defensively by element count
    const float *z = nullptr, *varq = nullptr, *cb = nullptr, *gum = nullptr;
    for (int i = 0; i < n_in; i++) {
        switch (in_sizes[i]) {
            case 2097152:  z    = (const float*)d_in[i]; break;
            case 1:        varq = (const float*)d_in[i]; break;
            case 32768:    cb   = (const float*)d_in[i]; break;
            case 16777216: gum  = (const float*)d_in[i]; break;
            default: break;
        }
    }
    float* out = (float*)d_out;

    // idempotent, host-side only (not a stream op) — safe to call every time
    cudaFuncSetAttribute(main_kernel,
                         cudaFuncAttributeMaxDynamicSharedMemorySize, 109832);

    prep_kernel<<<2, 256>>>(cb);
    main_kernel<<<1024, 256, 109832>>>(z, varq, cb, gum, out);
    final_kernel<<<1, 512>>>(varq, out, out_size);
}

// round 12
// speedup vs baseline: 1.3411x; 1.3411x over previous
#include <cuda_runtime.h>
#include <math.h>

#define NROWS 32768
#define KDICT 512
#define DDIM  64
#define ZN    2097152   // 32*64*32*32

typedef unsigned long long u64;

// packed fp32x2 FMA (Blackwell): d = a*b + d elementwise on two packed floats
__device__ __forceinline__ void ffma2(u64& d, u64 a, u64 b) {
    asm("fma.rn.f32x2 %0, %1, %2, %0;" : "+l"(d) : "l"(a), "l"(b));
}
__device__ __forceinline__ u64 dup2(float x) {
    u64 r; unsigned xi = __float_as_uint(x);
    asm("mov.b64 %0, {%1, %1};" : "=l"(r) : "r"(xi));
    return r;
}
__device__ __forceinline__ void unpack2(float& lo, float& hi, u64 v) {
    unsigned a, b;
    asm("mov.b64 {%0, %1}, %2;" : "=r"(a), "=r"(b) : "l"(v));
    lo = __uint_as_float(a); hi = __uint_as_float(b);
}

// scratch (no allocations allowed)
__device__ float g_c2[512];
__device__ float g_avg[512];
__device__ float g_kldd;
__device__ float g_cont;

__device__ __forceinline__ float half_prec_from(const float* varq) {
    float vq = __ldg(varq);
    float p  = fminf(1.0f / fmaxf(vq, 1e-5f), 1e5f);
    return 0.5f * p;
}

// ---------------------------------------------------------------------------
__global__ void prep_kernel(const float* __restrict__ cb) {
    int t = blockIdx.x * blockDim.x + threadIdx.x;
    if (t == 0) { g_kldd = 0.f; g_cont = 0.f; }
    if (t < 512) {
        g_avg[t] = 0.f;
        const float4* row = (const float4*)(cb + (size_t)t * 64);
        float s = 0.f;
        #pragma unroll
        for (int i = 0; i < 16; i++) {
            float4 v = __ldg(row + i);
            s += v.x*v.x + v.y*v.y + v.z*v.z + v.w*v.w;
        }
        g_c2[t] = s;
    }
}

// ---------------------------------------------------------------------------
// main fused kernel: 1 block = 32 rows. smem layout unchanged (109832 B).
// ---------------------------------------------------------------------------
__global__ void __launch_bounds__(256, 2)
main_kernel(const float* __restrict__ z, const float* __restrict__ varq,
            const float* __restrict__ cb, const float* __restrict__ gum,
            float* __restrict__ out) {
    extern __shared__ float sm[];
    float* sL    = sm;
    float* sZ    = sm + 16416;
    float* sCB   = sm + 18464;
    float* sAvg  = sm + 26912;
    float* sScal = sm + 27424;
    float* sZ2   = sm + 27426;

    const int t     = threadIdx.x;
    const int nbase = blockIdx.x * 32;
    const int b     = nbase >> 10;
    const int nin   = nbase & 1023;
    const float hp  = half_prec_from(varq);

    for (int i = t; i < 512; i += 256) sAvg[i] = 0.f;
    if (t < 2) sScal[t] = 0.f;

    // ---- load z tile transposed: sZ[d*32 + r] ----
    const float* zb = z + (size_t)b * 65536 + nin;
    for (int idx = t; idx < 2048; idx += 256) {
        int d = idx >> 5, r = idx & 31;
        sZ[idx] = __ldg(zb + (size_t)d * 1024 + r);
    }
    __syncthreads();
    if (t < 32) {
        float s = 0.f;
        #pragma unroll 8
        for (int d = 0; d < 64; d++) { float v = sZ[d*32 + t]; s += v*v; }
        sZ2[t] = s;
    }

    // =========================== Phase A: ip = z @ cb^T (FFMA2) ============
    // thread tile: rows r0..r0+3, col pairs: p=2*kc+{0,1} -> cols
    //   p even: {c0+128kc, c0+64+128kc}; p odd: {c0+32+128kc, c0+96+128kc}
    const int r0 = (t & 7) * 4;
    const int c0 = t >> 3;
    u64 accP[4][8];
    #pragma unroll
    for (int i = 0; i < 4; i++)
        #pragma unroll
        for (int p = 0; p < 8; p++) accP[i][p] = 0ull;

    const float4* Z4    = (const float4*)sZ;   // row d: 8 float4 of 32 rows
    const u64*    CBP64 = (const u64*)sCB;     // [d][66] packed col-pairs

    for (int kc = 0; kc < 4; kc++) {
        __syncthreads();
        // load 128 codebook rows, store transposed+paired:
        //   pair slot [d][cp] = { cb[base+cp][d], cb[base+cp+64][d] }
        for (int idx = t; idx < 2048; idx += 256) {
            int c = idx >> 4, dq = idx & 15;
            float4 v = __ldg((const float4*)cb + (size_t)(kc*128 + c)*16 + dq);
            int h = c >> 6, cp = c & 63;
            int base = cp*2 + h;
            sCB[(dq*4+0)*132 + base] = v.x;
            sCB[(dq*4+1)*132 + base] = v.y;
            sCB[(dq*4+2)*132 + base] = v.z;
            sCB[(dq*4+3)*132 + base] = v.w;
        }
        __syncthreads();
        const int p0 = kc * 2;
        #pragma unroll 4
        for (int d = 0; d < 64; d++) {
            float4 av = Z4[d*8 + (t & 7)];           // rows r0..r0+3
            u64 b02 = CBP64[d*66 + c0];              // cols {c0, c0+64}
            u64 b13 = CBP64[d*66 + c0 + 32];         // cols {c0+32, c0+96}
            u64 a0 = dup2(av.x), a1 = dup2(av.y), a2 = dup2(av.z), a3 = dup2(av.w);
            ffma2(accP[0][p0+0], a0, b02); ffma2(accP[0][p0+1], a0, b13);
            ffma2(accP[1][p0+0], a1, b02); ffma2(accP[1][p0+1], a1, b13);
            ffma2(accP[2][p0+0], a2, b02); ffma2(accP[2][p0+1], a2, b13);
            ffma2(accP[3][p0+0], a3, b02); ffma2(accP[3][p0+1], a3, b13);
        }
    }
    __syncthreads();

    // write logits: logit = -hp*(z2 + c2 - 2*ip)
    #pragma unroll
    for (int i = 0; i < 4; i++) {
        float z2v = sZ2[r0 + i];
        #pragma unroll
        for (int p = 0; p < 8; p++) {
            int kc2 = p >> 1, half = p & 1;
            int clo = c0 + kc2*128 + half*32;
            float lo, hi; unpack2(lo, hi, accP[i][p]);
            sL[(r0+i)*513 + clo]      = -hp*(z2v + __ldg(&g_c2[clo])    - 2.f*lo);
            sL[(r0+i)*513 + clo + 64] = -hp*(z2v + __ldg(&g_c2[clo+64]) - 2.f*hi);
        }
    }
    __syncthreads();

    // ================= Phase B: softmax / gumbel-softmax (warp per row) ====
    {
        const int w = t >> 5, lane = t & 31;
        float pacc[16];
        #pragma unroll
        for (int j = 0; j < 16; j++) pacc[j] = 0.f;
        float kldd_local = 0.f;
        const float* gumb = gum + (size_t)nbase * 512;

        for (int rr = 0; rr < 4; rr++) {
            int r = w*4 + rr;
            float v[16];
            #pragma unroll
            for (int j = 0; j < 16; j++) v[j] = sL[r*513 + lane + 32*j];
            float m = v[0];
            #pragma unroll
            for (int j = 1; j < 16; j++) m = fmaxf(m, v[j]);
            #pragma unroll
            for (int o = 16; o; o >>= 1) m = fmaxf(m, __shfl_xor_sync(~0u, m, o));

            float e[16], s1 = 0.f, t1 = 0.f;
            #pragma unroll
            for (int j = 0; j < 16; j++) {
                float lc = fminf(fmaxf(v[j] - m, -50.f), 50.f);
                v[j] = lc;
                float ee = __expf(lc);
                e[j] = ee;
                s1 += ee; t1 += ee * lc;
            }
            #pragma unroll
            for (int o = 16; o; o >>= 1) {
                s1 += __shfl_xor_sync(~0u, s1, o);
                t1 += __shfl_xor_sync(~0u, t1, o);
            }
            float inv1 = 1.0f / s1;
            #pragma unroll
            for (int j = 0; j < 16; j++) pacc[j] += e[j] * inv1;
            kldd_local += t1 * inv1 - __logf(s1);

            // gumbel: inner log needs accuracy ONLY near u=1 (log1pf branch);
            // elsewhere the relative error of __logf (3 ulp) is harmless.
            const float* gr = gumb + (size_t)r * 512;
            #pragma unroll
            for (int j = 0; j < 16; j++) {
                float u  = __ldg(gr + lane + 32*j);
                float lu = (u > 0.5f) ? log1pf(u - 1.0f)
                                      : __logf(u + 1e-10f);
                float g  = -__logf(1e-10f - lu);
                v[j] = (v[j] + g) * 2.0f;
            }
            float m2 = v[0];
            #pragma unroll
            for (int j = 1; j < 16; j++) m2 = fmaxf(m2, v[j]);
            #pragma unroll
            for (int o = 16; o; o >>= 1) m2 = fmaxf(m2, __shfl_xor_sync(~0u, m2, o));
            float s2 = 0.f;
            #pragma unroll
            for (int j = 0; j < 16; j++) { float ee = __expf(v[j] - m2); e[j] = ee; s2 += ee; }
            #pragma unroll
            for (int o = 16; o; o >>= 1) s2 += __shfl_xor_sync(~0u, s2, o);
            float inv2 = 1.0f / s2;
            #pragma unroll
            for (int j = 0; j < 16; j++) sL[r*513 + lane + 32*j] = e[j] * inv2;
        }
        if (lane == 0) atomicAdd(&sScal[0], kldd_local);
        #pragma unroll
        for (int j = 0; j < 16; j++) atomicAdd(&sAvg[lane + 32*j], pacc[j]);
    }
    __syncthreads();

    for (int i = t; i < 512; i += 256) atomicAdd(&g_avg[i], sAvg[i]);
    if (t == 0) atomicAdd(&g_kldd, sScal[0]);

    // ======================= Phase C: z_q = enc @ cb (FFMA2) ===============
    {
        const int rc = t & 31, dg = t >> 5;   // row, d-group (8 d each)
        u64 accq[4] = {0ull, 0ull, 0ull, 0ull};  // d-pairs (0,1)(2,3)(4,5)(6,7)

        for (int kc = 0; kc < 4; kc++) {
            __syncthreads();
            for (int idx = t; idx < 2048; idx += 256)
                ((float4*)sCB)[idx] = __ldg((const float4*)cb + (size_t)kc*2048 + idx);
            __syncthreads();
            const u64* CB64 = (const u64*)sCB;   // row k: 32 u64 (64 floats)
            #pragma unroll 4
            for (int k = 0; k < 128; k++) {
                float e = sL[rc*513 + kc*128 + k];
                u64 ep = dup2(e);
                int base = k*32 + dg*4;
                ffma2(accq[0], ep, CB64[base + 0]);
                ffma2(accq[1], ep, CB64[base + 1]);
                ffma2(accq[2], ep, CB64[base + 2]);
                ffma2(accq[3], ep, CB64[base + 3]);
            }
        }

        float contl = 0.f;
        float* ob = out + (size_t)b * 65536 + nin;
        #pragma unroll
        for (int p = 0; p < 4; p++) {
            float lo, hi; unpack2(lo, hi, accq[p]);
            int d0 = dg*8 + p*2;
            float z0 = sZ[d0*32 + rc],  z1 = sZ[(d0+1)*32 + rc];
            float f0 = z0 - lo,         f1 = z1 - hi;
            contl += f0*f0 + f1*f1;
            ob[(size_t)d0     * 1024 + rc] = lo;
            ob[(size_t)(d0+1) * 1024 + rc] = hi;
        }
        atomicAdd(&sScal[1], contl);
    }
    __syncthreads();
    if (t == 0) atomicAdd(&g_cont, sScal[1]);
}

// ---------------------------------------------------------------------------
__global__ void final_kernel(const float* __restrict__ varq,
                             float* __restrict__ out, int out_size) {
    __shared__ float red[512];
    int t = threadIdx.x;
    float ap = fmaxf(g_avg[t] * (1.0f / 32768.0f), 1e-10f);
    red[t] = ap * __logf(ap + 1e-10f);
    __syncthreads();
    for (int o = 256; o; o >>= 1) {
        if (t < o) red[t] += red[t + o];
        __syncthreads();
    }
    if (t == 0) {
        float hp    = half_prec_from(varq);
        float loss  = (g_kldd + hp * g_cont) * (1.0f / 32.0f);
        float perpl = __expf(-red[0]);
        if (out_size >= ZN + 2)      { out[ZN] = loss; out[ZN + 1] = perpl; }
        else if (out_size == 2)      { out[0]  = loss; out[1]      = perpl; }
    }
}

// ---------------------------------------------------------------------------
extern "C" void kernel_launch(void* const* d_in, const int* in_sizes, int n_in,
                              void* d_out, int out_size) {
    const float *z = nullptr, *varq = nullptr, *cb = nullptr, *gum = nullptr;
    for (int i = 0; i < n_in; i++) {
        switch (in_sizes[i]) {
            case 2097152:  z    = (const float*)d_in[i]; break;
            case 1:        varq = (const float*)d_in[i]; break;
            case 32768:    cb   = (const float*)d_in[i]; break;
            case 16777216: gum  = (const float*)d_in[i]; break;
            default: break;
        }
    }
    float* out = (float*)d_out;

    cudaFuncSetAttribute(main_kernel,
                         cudaFuncAttributeMaxDynamicSharedMemorySize, 109832);

    prep_kernel<<<2, 256>>>(cb);
    main_kernel<<<1024, 256, 109832>>>(z, varq, cb, gum, out);
    final_kernel<<<1, 512>>>(varq, out, out_size);
}